// round 11
// baseline (speedup 1.0000x reference)
#include <cuda_runtime.h>
#include <cuda_bf16.h>
#include <cstdint>
#include <cstddef>

// Problem constants
#define BB 4
#define LL 1024
#define CC 256
#define DM 512      // d_model
#define DI 512      // d_inner
#define DS 16       // d_state
#define DR 32       // dt_rank
#define TT (BB*LL)  // 4096 tokens

// ---------------- scratch (__device__ globals: allocation-free) ----------------
__device__ float g_x0n[TT*CC];             // normalized input0
__device__ float g_weight[TT*CC];          // cw preact -> gate weight
__device__ float g_xz[TT*1024];            // (b,l,e) e in [0,1024)
__device__ float g_u[2][TT*DI];            // conv+silu output
__device__ float g_xdbl[2][TT*64];         // dt|B|C per token
__device__ float g_xpart[2][4][TT*64];     // split-K partials for xproj
__device__ float g_delta[2][TT*DI];
__device__ float g_y[2][TT*DI];
__device__ float g_o1[TT*DI];
__device__ float g_o2[TT*CC];
// bf16 activation split (reused: combined -> ycomb -> o1n)
__device__ __align__(16) __nv_bfloat16 g_abh[TT*DM];
__device__ __align__(16) __nv_bfloat16 g_abl[TT*DM];
// bf16 split of u (per direction), written by conv
__device__ __align__(16) __nv_bfloat16 g_uh[2][TT*DI];
__device__ __align__(16) __nv_bfloat16 g_ul[2][TT*DI];
// bf16 weight splits
__device__ __align__(16) __nv_bfloat16 g_cwh[CC*DM],   g_cwl[CC*DM];
__device__ __align__(16) __nv_bfloat16 g_iph[1024*DM], g_ipl[1024*DM];
__device__ __align__(16) __nv_bfloat16 g_oph[DM*DI],   g_opl[DM*DI];
__device__ __align__(16) __nv_bfloat16 g_pbh[CC*DM],   g_pbl[CC*DM];
__device__ __align__(16) __nv_bfloat16 g_xwh[2][64*DI], g_xwl[2][64*DI];

// ---------------- helpers ----------------
__device__ __forceinline__ float cleanf(float x) {
    if (isnan(x)) return 0.f;
    if (isinf(x)) return x > 0.f ? 1.f : -1.f;
    return x;
}
__device__ __forceinline__ float siluf(float x) {
    return x / (1.f + __expf(-x));
}
__device__ __forceinline__ void split1(float x, __nv_bfloat16& h, __nv_bfloat16& l) {
    h = __float2bfloat16(x);
    l = __float2bfloat16(x - __bfloat162float(h));
}

template<int NW>
__device__ __forceinline__ float2 blockReduce2(float a, float b, float* sm) {
    __syncthreads();
    const unsigned full = 0xffffffffu;
    #pragma unroll
    for (int o = 16; o > 0; o >>= 1) {
        a += __shfl_xor_sync(full, a, o);
        b += __shfl_xor_sync(full, b, o);
    }
    int w = threadIdx.x >> 5, ln = threadIdx.x & 31;
    if (ln == 0) { sm[w] = a; sm[NW + w] = b; }
    __syncthreads();
    if (threadIdx.x < 32) {
        a = (ln < NW) ? sm[ln] : 0.f;
        b = (ln < NW) ? sm[NW + ln] : 0.f;
        #pragma unroll
        for (int o = 16; o > 0; o >>= 1) {
            a += __shfl_xor_sync(full, a, o);
            b += __shfl_xor_sync(full, b, o);
        }
        if (ln == 0) { sm[0] = a; sm[1] = b; }
    }
    __syncthreads();
    return make_float2(sm[0], sm[1]);
}

// ---------------- kernel 1: nan_to_num + LN inputs -> bf16 split of combined ----------------
__global__ void k_ln_inputs(const float* __restrict__ i0, const float* __restrict__ i1,
                            const float* __restrict__ g0, const float* __restrict__ b0,
                            const float* __restrict__ g1, const float* __restrict__ b1) {
    __shared__ float sm[32];
    int t = blockIdx.x, c = threadIdx.x;
    float v0 = cleanf(i0[t*CC + c]);
    float v1 = cleanf(i1[t*CC + c]);
    float2 s0 = blockReduce2<8>(v0, v0*v0, sm);
    float m0 = s0.x * (1.f/CC);
    float var0 = s0.y * (1.f/CC) - m0*m0;
    float x0 = (v0 - m0) * rsqrtf(var0 + 1e-5f) * g0[c] + b0[c];
    g_x0n[t*CC + c] = x0;
    split1(x0, g_abh[t*DM + c], g_abl[t*DM + c]);
    float2 s1 = blockReduce2<8>(v1, v1*v1, sm);
    float m1 = s1.x * (1.f/CC);
    float var1 = s1.y * (1.f/CC) - m1*m1;
    float x1 = (v1 - m1) * rsqrtf(var1 + 1e-5f) * g1[c] + b1[c];
    split1(x1, g_abh[t*DM + CC + c], g_abl[t*DM + CC + c]);
}

// ---------------- weight split: all six weight matrices in one kernel ----------------
__global__ void k_split_w(const float* __restrict__ cw, const float* __restrict__ ip,
                          const float* __restrict__ op, const float* __restrict__ pb,
                          const float* __restrict__ xpf, const float* __restrict__ xpb) {
    int v = blockIdx.x * blockDim.x + threadIdx.x;   // vec4 index, 278528 total
    const float* src; __nv_bfloat16 *h, *l; int off;
    if (v < 32768)        { src = cw;  h = g_cwh;    l = g_cwl;    off = v; }
    else if (v < 163840)  { src = ip;  h = g_iph;    l = g_ipl;    off = v - 32768; }
    else if (v < 229376)  { src = op;  h = g_oph;    l = g_opl;    off = v - 163840; }
    else if (v < 262144)  { src = pb;  h = g_pbh;    l = g_pbl;    off = v - 229376; }
    else if (v < 270336)  { src = xpf; h = g_xwh[0]; l = g_xwl[0]; off = v - 262144; }
    else                  { src = xpb; h = g_xwh[1]; l = g_xwl[1]; off = v - 270336; }
    float4 x = *reinterpret_cast<const float4*>(src + (size_t)off*4);
    const float* xp = &x.x;
    #pragma unroll
    for (int j = 0; j < 4; j++) split1(xp[j], h[off*4 + j], l[off*4 + j]);
}

// ---------------- cp.async helpers ----------------
__device__ __forceinline__ void cpa16(void* dst, const void* src) {
    uint32_t s = (uint32_t)__cvta_generic_to_shared(dst);
    asm volatile("cp.async.cg.shared.global [%0], [%1], 16;\n" :: "r"(s), "l"(src));
}
__device__ __forceinline__ void cp_commit() { asm volatile("cp.async.commit_group;\n"); }
__device__ __forceinline__ void cp_wait0()  { asm volatile("cp.async.wait_group 0;\n"); }
__device__ __forceinline__ void cp_wait1()  { asm volatile("cp.async.wait_group 1;\n"); }
__device__ __forceinline__ void cp_wait2()  { asm volatile("cp.async.wait_group 2;\n"); }

__device__ __forceinline__ void mma16816(float c[4], const uint32_t a[4], const uint32_t b[2]) {
    asm volatile("mma.sync.aligned.m16n8k16.row.col.f32.bf16.bf16.f32 "
        "{%0,%1,%2,%3}, {%4,%5,%6,%7}, {%8,%9}, {%0,%1,%2,%3};"
        : "+f"(c[0]), "+f"(c[1]), "+f"(c[2]), "+f"(c[3])
        : "r"(a[0]), "r"(a[1]), "r"(a[2]), "r"(a[3]), "r"(b[0]), "r"(b[1]));
}

// ---------------- tensor-core GEMM: fused 3-term bf16 split, cp.async 3-stage ----------------
// C[M,N] = A[M,K] * W[N,K]^T ~= Ah*Wh + Al*Wh + Ah*Wl.  BN=64, BK=16, 3-stage dynamic smem.
// EPI: 0 = store, 1 = +bias, 2 = split-K partial (out += blockIdx.z * TT*64, KS per slice)
template<int BM, int EPI, int SPLITK>
__global__ void __launch_bounds__(BM == 128 ? 256 : 128)
k_gemm_bf16(const __nv_bfloat16* __restrict__ Ah, const __nv_bfloat16* __restrict__ Al,
            const __nv_bfloat16* __restrict__ Wh, const __nv_bfloat16* __restrict__ Wl,
            const float* __restrict__ bias, float* __restrict__ C, int ldc, int K, int KS) {
    constexpr int THREADS = (BM == 128) ? 256 : 128;
    constexpr int STR = 48;                 // bytes/row: 32B data + 16B pad (conflict-free)
    constexpr int STAGE = (2*BM + 128) * STR;
    extern __shared__ unsigned char dsm[];
    const int tid = threadIdx.x;
    const int wid = tid >> 5, lane = tid & 31;
    const int warp_m = (wid >> 1) * 32;
    const int warp_n = (wid & 1) * 32;
    const int m0 = blockIdx.y * BM;
    const int n0 = blockIdx.x * 64;
    const int kb = SPLITK ? blockIdx.z * KS : 0;
    float* Cout = SPLITK ? (C + (size_t)blockIdx.z * (TT*64)) : C;

    float c[2][4][4];
    #pragma unroll
    for (int i = 0; i < 2; i++)
        #pragma unroll
        for (int j = 0; j < 4; j++)
            #pragma unroll
            for (int q = 0; q < 4; q++) c[i][j][q] = 0.f;

    auto load_stage = [&](int s, int k0) {
        unsigned char* base = dsm + s*STAGE;
        #pragma unroll
        for (int f = tid; f < BM*2; f += THREADS) {
            int m = f >> 1, hh = f & 1;
            size_t go = (size_t)(m0 + m)*K + k0 + hh*8;
            cpa16(base + m*STR + hh*16, Ah + go);
            cpa16(base + BM*STR + m*STR + hh*16, Al + go);
        }
        #pragma unroll
        for (int f = tid; f < 128; f += THREADS) {
            int n = f >> 1, hh = f & 1;
            size_t go = (size_t)(n0 + n)*K + k0 + hh*8;
            cpa16(base + 2*BM*STR + n*STR + hh*16, Wh + go);
            cpa16(base + 2*BM*STR + 64*STR + n*STR + hh*16, Wl + go);
        }
    };

    const int NK = KS / 16;
    load_stage(0, kb); cp_commit();
    load_stage(1, kb + 16); cp_commit();

    for (int ks = 0; ks < NK; ks++) {
        if (ks + 2 < NK) {
            load_stage((ks + 2) % 3, kb + (ks + 2) * 16);
            cp_commit();
            cp_wait2();
        } else if (ks + 1 < NK) {
            cp_wait1();
        } else {
            cp_wait0();
        }
        __syncthreads();

        const unsigned char* base = dsm + (ks % 3)*STAGE;
        const unsigned char* Ahb = base;
        const unsigned char* Alb = base + BM*STR;
        const unsigned char* Whb = base + 2*BM*STR;
        const unsigned char* Wlb = base + 2*BM*STR + 64*STR;

        uint32_t fah[2][4], fal[2][4];
        #pragma unroll
        for (int mf = 0; mf < 2; mf++) {
            int r = warp_m + mf*16 + (lane >> 2);
            const unsigned char* p = Ahb + r*STR + (lane & 3)*4;
            const unsigned char* q = Alb + r*STR + (lane & 3)*4;
            fah[mf][0] = *reinterpret_cast<const uint32_t*>(p);
            fah[mf][1] = *reinterpret_cast<const uint32_t*>(p + 8*STR);
            fah[mf][2] = *reinterpret_cast<const uint32_t*>(p + 16);
            fah[mf][3] = *reinterpret_cast<const uint32_t*>(p + 8*STR + 16);
            fal[mf][0] = *reinterpret_cast<const uint32_t*>(q);
            fal[mf][1] = *reinterpret_cast<const uint32_t*>(q + 8*STR);
            fal[mf][2] = *reinterpret_cast<const uint32_t*>(q + 16);
            fal[mf][3] = *reinterpret_cast<const uint32_t*>(q + 8*STR + 16);
        }
        uint32_t fbh[4][2], fbl[4][2];
        #pragma unroll
        for (int nf = 0; nf < 4; nf++) {
            int n = warp_n + nf*8 + (lane >> 2);
            const unsigned char* p = Whb + n*STR + (lane & 3)*4;
            const unsigned char* q = Wlb + n*STR + (lane & 3)*4;
            fbh[nf][0] = *reinterpret_cast<const uint32_t*>(p);
            fbh[nf][1] = *reinterpret_cast<const uint32_t*>(p + 16);
            fbl[nf][0] = *reinterpret_cast<const uint32_t*>(q);
            fbl[nf][1] = *reinterpret_cast<const uint32_t*>(q + 16);
        }
        #pragma unroll
        for (int mf = 0; mf < 2; mf++)
            #pragma unroll
            for (int nf = 0; nf < 4; nf++) {
                mma16816(c[mf][nf], fah[mf], fbh[nf]);
                mma16816(c[mf][nf], fal[mf], fbh[nf]);
                mma16816(c[mf][nf], fah[mf], fbl[nf]);
            }
        __syncthreads();
    }

    #pragma unroll
    for (int mf = 0; mf < 2; mf++) {
        #pragma unroll
        for (int nf = 0; nf < 4; nf++) {
            int row = m0 + warp_m + mf*16 + (lane >> 2);
            int col = n0 + warp_n + nf*8 + (lane & 3)*2;
            float v0 = c[mf][nf][0], v1 = c[mf][nf][1];
            float v2 = c[mf][nf][2], v3 = c[mf][nf][3];
            if (EPI == 1) {
                float b0 = bias[col], b1 = bias[col+1];
                v0 += b0; v1 += b1; v2 += b0; v3 += b1;
            }
            *reinterpret_cast<float2*>(&Cout[(size_t)row*ldc + col]) = make_float2(v0, v1);
            *reinterpret_cast<float2*>(&Cout[(size_t)(row+8)*ldc + col]) = make_float2(v2, v3);
        }
    }
}

// ---------------- SIMT SGEMM (dt GEMMs, K=32) ----------------
template<int BM, int BN, int BK, int TM, int TN, int EPI>
__global__ void __launch_bounds__((BM/TM)*(BN/TN))
k_gemm(const float* __restrict__ A, int lda,
       const float* __restrict__ W, int ldw,
       const float* __restrict__ bias,
       float* __restrict__ C, int ldc, int K) {
    constexpr int THREADS = (BM/TM)*(BN/TN);
    __shared__ __align__(16) float As[BK][BM + 4];
    __shared__ __align__(16) float Ws[BK][BN + 4];
    const int tid = threadIdx.x;
    const int m0 = blockIdx.y * BM;
    const int n0 = blockIdx.x * BN;
    const int tn = (tid % (BN/TN)) * TN;
    const int tm = (tid / (BN/TN)) * TM;

    float acc[TM][TN];
    #pragma unroll
    for (int i = 0; i < TM; i++)
        #pragma unroll
        for (int j = 0; j < TN; j++) acc[i][j] = 0.f;

    constexpr int A4 = BM*BK/4;
    constexpr int W4 = BN*BK/4;

    for (int k0 = 0; k0 < K; k0 += BK) {
        __syncthreads();
        #pragma unroll
        for (int f = tid; f < A4; f += THREADS) {
            int m = f / (BK/4), kq = f % (BK/4);
            float4 v = *reinterpret_cast<const float4*>(&A[(size_t)(m0+m)*lda + k0 + kq*4]);
            As[kq*4+0][m] = v.x; As[kq*4+1][m] = v.y;
            As[kq*4+2][m] = v.z; As[kq*4+3][m] = v.w;
        }
        #pragma unroll
        for (int f = tid; f < W4; f += THREADS) {
            int n = f / (BK/4), kq = f % (BK/4);
            float4 v = *reinterpret_cast<const float4*>(&W[(size_t)(n0+n)*ldw + k0 + kq*4]);
            Ws[kq*4+0][n] = v.x; Ws[kq*4+1][n] = v.y;
            Ws[kq*4+2][n] = v.z; Ws[kq*4+3][n] = v.w;
        }
        __syncthreads();
        #pragma unroll
        for (int kk = 0; kk < BK; kk++) {
            float ra[TM], rw[TN];
            #pragma unroll
            for (int i = 0; i < TM; i += 4)
                *reinterpret_cast<float4*>(&ra[i]) =
                    *reinterpret_cast<const float4*>(&As[kk][tm + i]);
            #pragma unroll
            for (int j = 0; j < TN; j += 4)
                *reinterpret_cast<float4*>(&rw[j]) =
                    *reinterpret_cast<const float4*>(&Ws[kk][tn + j]);
            #pragma unroll
            for (int i = 0; i < TM; i++)
                #pragma unroll
                for (int j = 0; j < TN; j++)
                    acc[i][j] = fmaf(ra[i], rw[j], acc[i][j]);
        }
    }

    #pragma unroll
    for (int i = 0; i < TM; i++) {
        #pragma unroll
        for (int j0 = 0; j0 < TN; j0 += 4) {
            float4 v;
            float* vp = &v.x;
            #pragma unroll
            for (int j = 0; j < 4; j++) {
                float x = acc[i][j0+j];
                if (EPI >= 1) x += bias[n0 + tn + j0 + j];
                if (EPI == 2) x = (x > 20.f) ? x : log1pf(__expf(x));
                vp[j] = x;
            }
            *reinterpret_cast<float4*>(&C[(size_t)(m0 + tm + i)*ldc + n0 + tn + j0]) = v;
        }
    }
}

__global__ void k_xreduce() {
    int i = blockIdx.x * blockDim.x + threadIdx.x;
    int dir = (i >= TT*64) ? 1 : 0;
    int j = i - dir * (TT*64);
    float s = (g_xpart[dir][0][j] + g_xpart[dir][1][j])
            + (g_xpart[dir][2][j] + g_xpart[dir][3][j]);
    g_xdbl[dir][j] = s;
}

// ---------------- LN(cwln) + sigmoid + clip ----------------
__global__ void k_cwln(const float* __restrict__ g, const float* __restrict__ b) {
    __shared__ float sm[32];
    int t = blockIdx.x, c = threadIdx.x;
    float v = g_weight[t*CC + c];
    float2 s = blockReduce2<8>(v, v*v, sm);
    float m = s.x * (1.f/CC);
    float var = s.y * (1.f/CC) - m*m;
    float x = (v - m) * rsqrtf(var + 1e-5f) * g[c] + b[c];
    float w = 1.f / (1.f + __expf(-x));
    w = fminf(fmaxf(w, 0.01f), 0.99f);
    g_weight[t*CC + c] = w;
}

// ---------------- depthwise causal conv + silu (+ bf16 split of u) ----------------
#define CONV_CHUNK 64
__global__ void k_conv(const float* __restrict__ cwf, const float* __restrict__ cbf,
                       const float* __restrict__ cwb, const float* __restrict__ cbb) {
    int d = threadIdx.x;
    int b = blockIdx.y;
    int dir = blockIdx.z;
    int t0 = blockIdx.x * CONV_CHUNK;
    const float* w = dir ? cwb : cwf;
    float w0 = w[d*4+0], w1 = w[d*4+1], w2 = w[d*4+2], w3 = w[d*4+3];
    float bias = (dir ? cbb : cbf)[d];
    size_t base = (size_t)b * LL;

    auto fetch = [&](int t) -> float {
        if (t < 0) return 0.f;
        int l = dir ? (LL - 1 - t) : t;
        return g_xz[(base + l)*1024 + d];
    };

    float r0 = fetch(t0-3), r1 = fetch(t0-2), r2 = fetch(t0-1);
    float* uo = g_u[dir];
    __nv_bfloat16* uh = g_uh[dir];
    __nv_bfloat16* ul = g_ul[dir];
    #pragma unroll 4
    for (int i = 0; i < CONV_CHUNK; i++) {
        int t = t0 + i;
        float x3 = fetch(t);
        float accv = bias + w0*r0 + w1*r1 + w2*r2 + w3*x3;
        float s = siluf(accv);
        size_t idx = (base + t)*DI + d;
        uo[idx] = s;
        split1(s, uh[idx], ul[idx]);
        r0 = r1; r1 = r2; r2 = x3;
    }
}

// ---------------- selective scan ----------------
__global__ void k_scan(const float* __restrict__ Alf, const float* __restrict__ Alb,
                       const float* __restrict__ Df,  const float* __restrict__ Db) {
    int gid = blockIdx.x * blockDim.x + threadIdx.x;
    int l   = gid & 7;
    int d   = (gid >> 3) & 511;
    int b   = (gid >> 12) & 3;
    int dir = (gid >> 14) & 1;
    const unsigned full = 0xffffffffu;

    const float* Al = dir ? Alb : Alf;
    float a0 = -__expf(Al[d*DS + l*2 + 0]);
    float a1 = -__expf(Al[d*DS + l*2 + 1]);
    float Dv = (dir ? Db : Df)[d];

    const float* dl = g_delta[dir];
    const float* uu = g_u[dir];
    const float* xd = g_xdbl[dir];
    float* yo = g_y[dir];

    size_t base = (size_t)b * LL;
    float h0 = 0.f, h1 = 0.f;

    float  cd[4], cu[4], cz[4];
    float2 cB[4], cC[4];
    #pragma unroll
    for (int j = 0; j < 4; j++) {
        size_t row = base + j;
        cd[j] = dl[row*DI + d];
        cu[j] = uu[row*DI + d];
        cB[j] = *reinterpret_cast<const float2*>(xd + row*64 + 32 + l*2);
        cC[j] = *reinterpret_cast<const float2*>(xd + row*64 + 48 + l*2);
        int lq = dir ? (LL - 1 - j) : j;
        cz[j] = g_xz[(base + lq)*1024 + DI + d];
    }

    for (int t0 = 0; t0 < LL; t0 += 4) {
        float  nd[4] = {0,0,0,0}, nu[4] = {0,0,0,0}, nz[4] = {0,0,0,0};
        float2 nB[4] = {}, nC[4] = {};
        if (t0 + 4 < LL) {
            #pragma unroll
            for (int j = 0; j < 4; j++) {
                size_t row = base + t0 + 4 + j;
                nd[j] = dl[row*DI + d];
                nu[j] = uu[row*DI + d];
                nB[j] = *reinterpret_cast<const float2*>(xd + row*64 + 32 + l*2);
                nC[j] = *reinterpret_cast<const float2*>(xd + row*64 + 48 + l*2);
                int lq = dir ? (LL - 1 - (t0 + 4 + j)) : (t0 + 4 + j);
                nz[j] = g_xz[(base + lq)*1024 + DI + d];
            }
        }
        #pragma unroll
        for (int j = 0; j < 4; j++) {
            int t = t0 + j;
            float delta = cd[j], u = cu[j];
            float du = delta * u;
            h0 = fmaf(__expf(delta * a0), h0, du * cB[j].x);
            h1 = fmaf(__expf(delta * a1), h1, du * cB[j].y);
            float y = h0 * cC[j].x + h1 * cC[j].y;
            y += __shfl_xor_sync(full, y, 1);
            y += __shfl_xor_sync(full, y, 2);
            y += __shfl_xor_sync(full, y, 4);
            y = fmaf(Dv, u, y);
            y *= siluf(cz[j]);
            if (l == 0) yo[(base + t)*DI + d] = y;
        }
        #pragma unroll
        for (int j = 0; j < 4; j++) {
            cd[j] = nd[j]; cu[j] = nu[j]; cz[j] = nz[j];
            cB[j] = nB[j]; cC[j] = nC[j];
        }
    }
}

// ---------------- combine directions + mnorm LN -> bf16 split ----------------
__global__ void k_combine(const float* __restrict__ g, const float* __restrict__ b_) {
    __shared__ float sm[32];
    int t = blockIdx.x;
    int b = t >> 10, l = t & (LL - 1);
    int d = threadIdx.x;
    float v = 0.5f * (g_y[0][(size_t)t*DI + d] +
                      g_y[1][((size_t)b*LL + (LL - 1 - l))*DI + d]);
    float2 s = blockReduce2<16>(v, v*v, sm);
    float m = s.x * (1.f/DI);
    float var = s.y * (1.f/DI) - m*m;
    float x = (v - m) * rsqrtf(var + 1e-5f) * g[d] + b_[d];
    split1(x, g_abh[(size_t)t*DI + d], g_abl[(size_t)t*DI + d]);
}

// ---------------- pnorm LN -> bf16 split ----------------
__global__ void k_pnorm(const float* __restrict__ g, const float* __restrict__ b) {
    __shared__ float sm[32];
    int t = blockIdx.x, d = threadIdx.x;
    float v = g_o1[(size_t)t*DM + d];
    float2 s = blockReduce2<16>(v, v*v, sm);
    float m = s.x * (1.f/DM);
    float var = s.y * (1.f/DM) - m*m;
    float x = (v - m) * rsqrtf(var + 1e-5f) * g[d] + b[d];
    split1(x, g_abh[(size_t)t*DM + d], g_abl[(size_t)t*DM + d]);
}

// ---------------- final blend ----------------
__global__ void k_final(const float* __restrict__ i0, float* __restrict__ out) {
    int idx = blockIdx.x * blockDim.x + threadIdx.x;
    float v = cleanf(g_o2[idx]);
    float w = g_weight[idx];
    out[idx] = v*w + g_x0n[idx]*(1.f - w) + cleanf(i0[idx]);
}

// ---------------- launch ----------------
extern "C" void kernel_launch(void* const* d_in, const int* in_sizes, int n_in,
                              void* d_out, int out_size) {
    const float* input0   = (const float*)d_in[0];
    const float* input1   = (const float*)d_in[1];
    const float* norm0_g  = (const float*)d_in[2];
    const float* norm0_b  = (const float*)d_in[3];
    const float* norm1_g  = (const float*)d_in[4];
    const float* norm1_b  = (const float*)d_in[5];
    const float* in_proj_w= (const float*)d_in[6];

    const float *convf_w, *convf_b, *convb_w, *convb_b;
    const float *xprojf_w, *xprojb_w, *dtf_w, *dtf_b, *dtb_w, *dtb_b;
    const float *A_log_f, *A_log_b, *D_f, *D_b;
    const float *mnorm_g, *mnorm_b, *outproj_w, *pnorm_g, *pnorm_b;
    const float *projback_w, *projback_b, *cw_w, *cw_b, *cwln_g, *cwln_b;

    if (in_sizes[9] == 2048) {
        convf_w    = (const float*)d_in[7];
        convf_b    = (const float*)d_in[8];
        convb_w    = (const float*)d_in[9];
        convb_b    = (const float*)d_in[10];
        xprojf_w   = (const float*)d_in[11];
        xprojb_w   = (const float*)d_in[12];
        dtf_w      = (const float*)d_in[13];
        dtf_b      = (const float*)d_in[14];
        dtb_w      = (const float*)d_in[15];
        dtb_b      = (const float*)d_in[16];
        A_log_f    = (const float*)d_in[17];
        A_log_b    = (const float*)d_in[18];
        D_f        = (const float*)d_in[19];
        D_b        = (const float*)d_in[20];
    } else {
        // setup_inputs dict-insertion order (confirmed on HW)
        convf_w    = (const float*)d_in[7];
        convf_b    = (const float*)d_in[8];
        xprojf_w   = (const float*)d_in[9];
        dtf_w      = (const float*)d_in[10];
        dtf_b      = (const float*)d_in[11];
        A_log_f    = (const float*)d_in[12];
        D_f        = (const float*)d_in[13];
        convb_w    = (const float*)d_in[14];
        convb_b    = (const float*)d_in[15];
        xprojb_w   = (const float*)d_in[16];
        dtb_w      = (const float*)d_in[17];
        dtb_b      = (const float*)d_in[18];
        A_log_b    = (const float*)d_in[19];
        D_b        = (const float*)d_in[20];
    }
    mnorm_g    = (const float*)d_in[21];
    mnorm_b    = (const float*)d_in[22];
    outproj_w  = (const float*)d_in[23];
    pnorm_g    = (const float*)d_in[24];
    pnorm_b    = (const float*)d_in[25];
    projback_w = (const float*)d_in[26];
    projback_b = (const float*)d_in[27];
    cw_w       = (const float*)d_in[28];
    cw_b       = (const float*)d_in[29];
    cwln_g     = (const float*)d_in[30];
    cwln_b     = (const float*)d_in[31];
    float* out = (float*)d_out;

    float *weight, *xz, *u0, *xdbl0, *xpart, *delta0, *o1, *o2;
    __nv_bfloat16 *abh, *abl, *cwh, *cwl, *iph, *ipl, *oph, *opl, *pbh, *pbl;
    __nv_bfloat16 *uh, *ul, *xwh, *xwl;
    cudaGetSymbolAddress((void**)&weight,   g_weight);
    cudaGetSymbolAddress((void**)&xz,       g_xz);
    cudaGetSymbolAddress((void**)&u0,       g_u);
    cudaGetSymbolAddress((void**)&xdbl0,    g_xdbl);
    cudaGetSymbolAddress((void**)&xpart,    g_xpart);
    cudaGetSymbolAddress((void**)&delta0,   g_delta);
    cudaGetSymbolAddress((void**)&o1,       g_o1);
    cudaGetSymbolAddress((void**)&o2,       g_o2);
    cudaGetSymbolAddress((void**)&abh,      g_abh);
    cudaGetSymbolAddress((void**)&abl,      g_abl);
    cudaGetSymbolAddress((void**)&cwh,      g_cwh);
    cudaGetSymbolAddress((void**)&cwl,      g_cwl);
    cudaGetSymbolAddress((void**)&iph,      g_iph);
    cudaGetSymbolAddress((void**)&ipl,      g_ipl);
    cudaGetSymbolAddress((void**)&oph,      g_oph);
    cudaGetSymbolAddress((void**)&opl,      g_opl);
    cudaGetSymbolAddress((void**)&pbh,      g_pbh);
    cudaGetSymbolAddress((void**)&pbl,      g_pbl);
    cudaGetSymbolAddress((void**)&uh,       g_uh);
    cudaGetSymbolAddress((void**)&ul,       g_ul);
    cudaGetSymbolAddress((void**)&xwh,      g_xwh);
    cudaGetSymbolAddress((void**)&xwl,      g_xwl);
    float* xdbl1  = xdbl0  + (size_t)TT*64;
    float* xpart0 = xpart;
    float* xpart1 = xpart  + (size_t)4*TT*64;
    float* delta1 = delta0 + (size_t)TT*DI;
    __nv_bfloat16* uh0 = uh;
    __nv_bfloat16* uh1 = uh + (size_t)TT*DI;
    __nv_bfloat16* ul0 = ul;
    __nv_bfloat16* ul1 = ul + (size_t)TT*DI;
    __nv_bfloat16* xwh0 = xwh;
    __nv_bfloat16* xwh1 = xwh + (size_t)64*DI;
    __nv_bfloat16* xwl0 = xwl;
    __nv_bfloat16* xwl1 = xwl + (size_t)64*DI;

    // dynamic smem opt-in for the BM=128 GEMM (3 stages x 18432 B)
    const int SMEM128 = 3 * (2*128 + 128) * 48;   // 55296
    const int SMEM64  = 3 * (2*64  + 128) * 48;   // 36864
    cudaFuncSetAttribute(k_gemm_bf16<128,0,0>, cudaFuncAttributeMaxDynamicSharedMemorySize, SMEM128);

    // 0. split all weights (one kernel)
    k_split_w<<<1088, 256>>>(cw_w, in_proj_w, outproj_w, projback_w, xprojf_w, xprojb_w);

    // 1. input LayerNorms -> x0n + bf16 split of combined
    k_ln_inputs<<<TT, 256>>>(input0, input1, norm0_g, norm0_b, norm1_g, norm1_b);

    // 2. cw GEMM (tensor): (4096x512)@(256x512)^T + bias
    k_gemm_bf16<64,1,0><<<dim3(CC/64, TT/64), 128, SMEM64>>>(abh, abl, cwh, cwl, cw_b, weight, CC, DM, DM);
    // 3. cw LN + sigmoid + clip
    k_cwln<<<TT, 256>>>(cwln_g, cwln_b);

    // 4. in_proj GEMM (tensor): (4096x512)@(1024x512)^T
    k_gemm_bf16<128,0,0><<<dim3(1024/64, TT/128), 256, SMEM128>>>(abh, abl, iph, ipl, nullptr, xz, 1024, DM, DM);

    // 5. conv + silu + bf16 split of u, both directions
    k_conv<<<dim3(LL/CONV_CHUNK, BB, 2), 512>>>(convf_w, convf_b, convb_w, convb_b);

    // 6. x_dbl GEMMs (tensor, split-K 4), then reduce
    k_gemm_bf16<64,2,1><<<dim3(1, TT/64, 4), 128, SMEM64>>>(uh0, ul0, xwh0, xwl0, nullptr, xpart0, 64, DI, 128);
    k_gemm_bf16<64,2,1><<<dim3(1, TT/64, 4), 128, SMEM64>>>(uh1, ul1, xwh1, xwl1, nullptr, xpart1, 64, DI, 128);
    k_xreduce<<<2*TT*64/256, 256>>>();

    // 7. delta GEMMs (SIMT, K=32): (4096x32)@(512x32)^T + bias, softplus
    k_gemm<128,64,16,8,8,2><<<dim3(DI/64, TT/128), 128>>>(xdbl0, 64, dtf_w, DR, dtf_b, delta0, DI, DR);
    k_gemm<128,64,16,8,8,2><<<dim3(DI/64, TT/128), 128>>>(xdbl1, 64, dtb_w, DR, dtb_b, delta1, DI, DR);

    // 8. selective scan
    k_scan<<<128, 256>>>(A_log_f, A_log_b, D_f, D_b);

    // 9. combine + mnorm -> bf16 split
    k_combine<<<TT, 512>>>(mnorm_g, mnorm_b);

    // 10. out_proj GEMM (tensor): (4096x512)@(512x512)^T
    k_gemm_bf16<128,0,0><<<dim3(DM/64, TT/128), 256, SMEM128>>>(abh, abl, oph, opl, nullptr, o1, DM, DI, DI);

    // 11. pnorm -> bf16 split
    k_pnorm<<<TT, 512>>>(pnorm_g, pnorm_b);

    // 12. projback GEMM (tensor): (4096x512)@(256x512)^T + bias
    k_gemm_bf16<64,1,0><<<dim3(CC/64, TT/64), 128, SMEM64>>>(abh, abl, pbh, pbl, projback_b, o2, CC, DM, DM);

    // 13. final blend
    k_final<<<TT, 256>>>(input0, out);
}

// round 12
// speedup vs baseline: 1.0194x; 1.0194x over previous
#include <cuda_runtime.h>
#include <cuda_bf16.h>
#include <cstdint>
#include <cstddef>

// Problem constants
#define BB 4
#define LL 1024
#define CC 256
#define DM 512      // d_model
#define DI 512      // d_inner
#define DS 16       // d_state
#define DR 32       // dt_rank
#define TT (BB*LL)  // 4096 tokens

// ---------------- scratch (__device__ globals: allocation-free) ----------------
__device__ float g_x0n[TT*CC];             // normalized input0
__device__ float g_weight[TT*CC];          // cw preact -> gate weight
__device__ float g_xz[TT*1024];            // (b,l,e) e in [0,1024)
__device__ float g_u[2][TT*DI];            // conv+silu output
__device__ float g_xdbl[2][TT*64];         // dt|B|C per token
__device__ float g_xpart[2][4][TT*64];     // split-K partials for xproj
__device__ float g_delta[2][TT*DI];
__device__ float g_y[2][TT*DI];
__device__ float g_o1[TT*DI];
__device__ float g_o2[TT*CC];
// bf16 activation split (reused: combined -> ycomb -> o1n)
__device__ __align__(16) __nv_bfloat16 g_abh[TT*DM];
__device__ __align__(16) __nv_bfloat16 g_abl[TT*DM];
// bf16 split of u (per direction), written by conv
__device__ __align__(16) __nv_bfloat16 g_uh[2][TT*DI];
__device__ __align__(16) __nv_bfloat16 g_ul[2][TT*DI];
// bf16 weight splits
__device__ __align__(16) __nv_bfloat16 g_cwh[CC*DM],   g_cwl[CC*DM];
__device__ __align__(16) __nv_bfloat16 g_iph[1024*DM], g_ipl[1024*DM];
__device__ __align__(16) __nv_bfloat16 g_oph[DM*DI],   g_opl[DM*DI];
__device__ __align__(16) __nv_bfloat16 g_pbh[CC*DM],   g_pbl[CC*DM];
__device__ __align__(16) __nv_bfloat16 g_xwh[2][64*DI], g_xwl[2][64*DI];

// ---------------- helpers ----------------
__device__ __forceinline__ float cleanf(float x) {
    if (isnan(x)) return 0.f;
    if (isinf(x)) return x > 0.f ? 1.f : -1.f;
    return x;
}
__device__ __forceinline__ float siluf(float x) {
    return x / (1.f + __expf(-x));
}
__device__ __forceinline__ void split1(float x, __nv_bfloat16& h, __nv_bfloat16& l) {
    h = __float2bfloat16(x);
    l = __float2bfloat16(x - __bfloat162float(h));
}

template<int NW>
__device__ __forceinline__ float2 blockReduce2(float a, float b, float* sm) {
    __syncthreads();
    const unsigned full = 0xffffffffu;
    #pragma unroll
    for (int o = 16; o > 0; o >>= 1) {
        a += __shfl_xor_sync(full, a, o);
        b += __shfl_xor_sync(full, b, o);
    }
    int w = threadIdx.x >> 5, ln = threadIdx.x & 31;
    if (ln == 0) { sm[w] = a; sm[NW + w] = b; }
    __syncthreads();
    if (threadIdx.x < 32) {
        a = (ln < NW) ? sm[ln] : 0.f;
        b = (ln < NW) ? sm[NW + ln] : 0.f;
        #pragma unroll
        for (int o = 16; o > 0; o >>= 1) {
            a += __shfl_xor_sync(full, a, o);
            b += __shfl_xor_sync(full, b, o);
        }
        if (ln == 0) { sm[0] = a; sm[1] = b; }
    }
    __syncthreads();
    return make_float2(sm[0], sm[1]);
}

// ---------------- kernel 1: nan_to_num + LN inputs -> bf16 split of combined ----------------
__global__ void k_ln_inputs(const float* __restrict__ i0, const float* __restrict__ i1,
                            const float* __restrict__ g0, const float* __restrict__ b0,
                            const float* __restrict__ g1, const float* __restrict__ b1) {
    __shared__ float sm[32];
    int t = blockIdx.x, c = threadIdx.x;
    float v0 = cleanf(i0[t*CC + c]);
    float v1 = cleanf(i1[t*CC + c]);
    float2 s0 = blockReduce2<8>(v0, v0*v0, sm);
    float m0 = s0.x * (1.f/CC);
    float var0 = s0.y * (1.f/CC) - m0*m0;
    float x0 = (v0 - m0) * rsqrtf(var0 + 1e-5f) * g0[c] + b0[c];
    g_x0n[t*CC + c] = x0;
    split1(x0, g_abh[t*DM + c], g_abl[t*DM + c]);
    float2 s1 = blockReduce2<8>(v1, v1*v1, sm);
    float m1 = s1.x * (1.f/CC);
    float var1 = s1.y * (1.f/CC) - m1*m1;
    float x1 = (v1 - m1) * rsqrtf(var1 + 1e-5f) * g1[c] + b1[c];
    split1(x1, g_abh[t*DM + CC + c], g_abl[t*DM + CC + c]);
}

// ---------------- weight split: all six weight matrices in one kernel ----------------
__global__ void k_split_w(const float* __restrict__ cw, const float* __restrict__ ip,
                          const float* __restrict__ op, const float* __restrict__ pb,
                          const float* __restrict__ xpf, const float* __restrict__ xpb) {
    int v = blockIdx.x * blockDim.x + threadIdx.x;   // vec4 index, 278528 total
    const float* src; __nv_bfloat16 *h, *l; int off;
    if (v < 32768)        { src = cw;  h = g_cwh;    l = g_cwl;    off = v; }
    else if (v < 163840)  { src = ip;  h = g_iph;    l = g_ipl;    off = v - 32768; }
    else if (v < 229376)  { src = op;  h = g_oph;    l = g_opl;    off = v - 163840; }
    else if (v < 262144)  { src = pb;  h = g_pbh;    l = g_pbl;    off = v - 229376; }
    else if (v < 270336)  { src = xpf; h = g_xwh[0]; l = g_xwl[0]; off = v - 262144; }
    else                  { src = xpb; h = g_xwh[1]; l = g_xwl[1]; off = v - 270336; }
    float4 x = *reinterpret_cast<const float4*>(src + (size_t)off*4);
    const float* xp = &x.x;
    #pragma unroll
    for (int j = 0; j < 4; j++) split1(xp[j], h[off*4 + j], l[off*4 + j]);
}

// ---------------- cp.async helpers ----------------
__device__ __forceinline__ void cpa16(void* dst, const void* src) {
    uint32_t s = (uint32_t)__cvta_generic_to_shared(dst);
    asm volatile("cp.async.cg.shared.global [%0], [%1], 16;\n" :: "r"(s), "l"(src));
}
__device__ __forceinline__ void cp_commit() { asm volatile("cp.async.commit_group;\n"); }
__device__ __forceinline__ void cp_wait0()  { asm volatile("cp.async.wait_group 0;\n"); }
__device__ __forceinline__ void cp_wait1()  { asm volatile("cp.async.wait_group 1;\n"); }

__device__ __forceinline__ void mma16816(float c[4], const uint32_t a[4], const uint32_t b[2]) {
    asm volatile("mma.sync.aligned.m16n8k16.row.col.f32.bf16.bf16.f32 "
        "{%0,%1,%2,%3}, {%4,%5,%6,%7}, {%8,%9}, {%0,%1,%2,%3};"
        : "+f"(c[0]), "+f"(c[1]), "+f"(c[2]), "+f"(c[3])
        : "r"(a[0]), "r"(a[1]), "r"(a[2]), "r"(a[3]), "r"(b[0]), "r"(b[1]));
}

// ---------------- tensor-core GEMM: fused 3-term bf16 split, cp.async 2-stage (round-8 proven) ----------------
// C[M,N] = A[M,K] * W[N,K]^T ~= Ah*Wh + Al*Wh + Ah*Wl.  BN=64, BK=16, static smem.
// EPI: 0 = store, 1 = +bias.  SPLITK: 1 = partial store to C + blockIdx.z*TT*64, slice length KS.
template<int BM, int EPI, int SPLITK>
__global__ void __launch_bounds__(BM == 128 ? 256 : 128)
k_gemm_bf16(const __nv_bfloat16* __restrict__ Ah, const __nv_bfloat16* __restrict__ Al,
            const __nv_bfloat16* __restrict__ Wh, const __nv_bfloat16* __restrict__ Wl,
            const float* __restrict__ bias, float* __restrict__ C, int ldc, int K, int KS) {
    constexpr int THREADS = (BM == 128) ? 256 : 128;
    constexpr int STR = 48;   // bytes/row: 32B data + 16B pad
    __shared__ __align__(16) unsigned char sAh[2][BM*STR];
    __shared__ __align__(16) unsigned char sAl[2][BM*STR];
    __shared__ __align__(16) unsigned char sWh[2][64*STR];
    __shared__ __align__(16) unsigned char sWl[2][64*STR];
    const int tid = threadIdx.x;
    const int wid = tid >> 5, lane = tid & 31;
    const int warp_m = (wid >> 1) * 32;
    const int warp_n = (wid & 1) * 32;
    const int m0 = blockIdx.y * BM;
    const int n0 = blockIdx.x * 64;
    const int kb = SPLITK ? blockIdx.z * KS : 0;
    float* Cout = SPLITK ? (C + (size_t)blockIdx.z * (TT*64)) : C;

    float c[2][4][4];
    #pragma unroll
    for (int i = 0; i < 2; i++)
        #pragma unroll
        for (int j = 0; j < 4; j++)
            #pragma unroll
            for (int q = 0; q < 4; q++) c[i][j][q] = 0.f;

    auto load_stage = [&](int s, int k0) {
        #pragma unroll
        for (int f = tid; f < BM*2; f += THREADS) {
            int m = f >> 1, hh = f & 1;
            size_t go = (size_t)(m0 + m)*K + k0 + hh*8;
            cpa16(&sAh[s][m*STR + hh*16], Ah + go);
            cpa16(&sAl[s][m*STR + hh*16], Al + go);
        }
        #pragma unroll
        for (int f = tid; f < 128; f += THREADS) {
            int n = f >> 1, hh = f & 1;
            size_t go = (size_t)(n0 + n)*K + k0 + hh*8;
            cpa16(&sWh[s][n*STR + hh*16], Wh + go);
            cpa16(&sWl[s][n*STR + hh*16], Wl + go);
        }
    };

    const int NK = KS / 16;
    load_stage(0, kb);
    cp_commit();

    for (int ks = 0; ks < NK; ks++) {
        int cur = ks & 1;
        if (ks + 1 < NK) {
            load_stage(1 - cur, kb + (ks + 1) * 16);
            cp_commit();
            cp_wait1();
        } else {
            cp_wait0();
        }
        __syncthreads();

        const unsigned char* Ahb = sAh[cur];
        const unsigned char* Alb = sAl[cur];
        const unsigned char* Whb = sWh[cur];
        const unsigned char* Wlb = sWl[cur];

        uint32_t fah[2][4], fal[2][4];
        #pragma unroll
        for (int mf = 0; mf < 2; mf++) {
            int r = warp_m + mf*16 + (lane >> 2);
            const unsigned char* p = Ahb + r*STR + (lane & 3)*4;
            const unsigned char* q = Alb + r*STR + (lane & 3)*4;
            fah[mf][0] = *reinterpret_cast<const uint32_t*>(p);
            fah[mf][1] = *reinterpret_cast<const uint32_t*>(p + 8*STR);
            fah[mf][2] = *reinterpret_cast<const uint32_t*>(p + 16);
            fah[mf][3] = *reinterpret_cast<const uint32_t*>(p + 8*STR + 16);
            fal[mf][0] = *reinterpret_cast<const uint32_t*>(q);
            fal[mf][1] = *reinterpret_cast<const uint32_t*>(q + 8*STR);
            fal[mf][2] = *reinterpret_cast<const uint32_t*>(q + 16);
            fal[mf][3] = *reinterpret_cast<const uint32_t*>(q + 8*STR + 16);
        }
        uint32_t fbh[4][2], fbl[4][2];
        #pragma unroll
        for (int nf = 0; nf < 4; nf++) {
            int n = warp_n + nf*8 + (lane >> 2);
            const unsigned char* p = Whb + n*STR + (lane & 3)*4;
            const unsigned char* q = Wlb + n*STR + (lane & 3)*4;
            fbh[nf][0] = *reinterpret_cast<const uint32_t*>(p);
            fbh[nf][1] = *reinterpret_cast<const uint32_t*>(p + 16);
            fbl[nf][0] = *reinterpret_cast<const uint32_t*>(q);
            fbl[nf][1] = *reinterpret_cast<const uint32_t*>(q + 16);
        }
        #pragma unroll
        for (int mf = 0; mf < 2; mf++)
            #pragma unroll
            for (int nf = 0; nf < 4; nf++) {
                mma16816(c[mf][nf], fah[mf], fbh[nf]);
                mma16816(c[mf][nf], fal[mf], fbh[nf]);
                mma16816(c[mf][nf], fah[mf], fbl[nf]);
            }
        __syncthreads();
    }

    #pragma unroll
    for (int mf = 0; mf < 2; mf++) {
        #pragma unroll
        for (int nf = 0; nf < 4; nf++) {
            int row = m0 + warp_m + mf*16 + (lane >> 2);
            int col = n0 + warp_n + nf*8 + (lane & 3)*2;
            float v0 = c[mf][nf][0], v1 = c[mf][nf][1];
            float v2 = c[mf][nf][2], v3 = c[mf][nf][3];
            if (EPI == 1) {
                float b0 = bias[col], b1 = bias[col+1];
                v0 += b0; v1 += b1; v2 += b0; v3 += b1;
            }
            *reinterpret_cast<float2*>(&Cout[(size_t)row*ldc + col]) = make_float2(v0, v1);
            *reinterpret_cast<float2*>(&Cout[(size_t)(row+8)*ldc + col]) = make_float2(v2, v3);
        }
    }
}

// ---------------- SIMT SGEMM (dt GEMMs, K=32) ----------------
template<int BM, int BN, int BK, int TM, int TN, int EPI>
__global__ void __launch_bounds__((BM/TM)*(BN/TN))
k_gemm(const float* __restrict__ A, int lda,
       const float* __restrict__ W, int ldw,
       const float* __restrict__ bias,
       float* __restrict__ C, int ldc, int K) {
    constexpr int THREADS = (BM/TM)*(BN/TN);
    __shared__ __align__(16) float As[BK][BM + 4];
    __shared__ __align__(16) float Ws[BK][BN + 4];
    const int tid = threadIdx.x;
    const int m0 = blockIdx.y * BM;
    const int n0 = blockIdx.x * BN;
    const int tn = (tid % (BN/TN)) * TN;
    const int tm = (tid / (BN/TN)) * TM;

    float acc[TM][TN];
    #pragma unroll
    for (int i = 0; i < TM; i++)
        #pragma unroll
        for (int j = 0; j < TN; j++) acc[i][j] = 0.f;

    constexpr int A4 = BM*BK/4;
    constexpr int W4 = BN*BK/4;

    for (int k0 = 0; k0 < K; k0 += BK) {
        __syncthreads();
        #pragma unroll
        for (int f = tid; f < A4; f += THREADS) {
            int m = f / (BK/4), kq = f % (BK/4);
            float4 v = *reinterpret_cast<const float4*>(&A[(size_t)(m0+m)*lda + k0 + kq*4]);
            As[kq*4+0][m] = v.x; As[kq*4+1][m] = v.y;
            As[kq*4+2][m] = v.z; As[kq*4+3][m] = v.w;
        }
        #pragma unroll
        for (int f = tid; f < W4; f += THREADS) {
            int n = f / (BK/4), kq = f % (BK/4);
            float4 v = *reinterpret_cast<const float4*>(&W[(size_t)(n0+n)*ldw + k0 + kq*4]);
            Ws[kq*4+0][n] = v.x; Ws[kq*4+1][n] = v.y;
            Ws[kq*4+2][n] = v.z; Ws[kq*4+3][n] = v.w;
        }
        __syncthreads();
        #pragma unroll
        for (int kk = 0; kk < BK; kk++) {
            float ra[TM], rw[TN];
            #pragma unroll
            for (int i = 0; i < TM; i += 4)
                *reinterpret_cast<float4*>(&ra[i]) =
                    *reinterpret_cast<const float4*>(&As[kk][tm + i]);
            #pragma unroll
            for (int j = 0; j < TN; j += 4)
                *reinterpret_cast<float4*>(&rw[j]) =
                    *reinterpret_cast<const float4*>(&Ws[kk][tn + j]);
            #pragma unroll
            for (int i = 0; i < TM; i++)
                #pragma unroll
                for (int j = 0; j < TN; j++)
                    acc[i][j] = fmaf(ra[i], rw[j], acc[i][j]);
        }
    }

    #pragma unroll
    for (int i = 0; i < TM; i++) {
        #pragma unroll
        for (int j0 = 0; j0 < TN; j0 += 4) {
            float4 v;
            float* vp = &v.x;
            #pragma unroll
            for (int j = 0; j < 4; j++) {
                float x = acc[i][j0+j];
                if (EPI >= 1) x += bias[n0 + tn + j0 + j];
                if (EPI == 2) x = (x > 20.f) ? x : log1pf(__expf(x));
                vp[j] = x;
            }
            *reinterpret_cast<float4*>(&C[(size_t)(m0 + tm + i)*ldc + n0 + tn + j0]) = v;
        }
    }
}

__global__ void k_xreduce() {
    int i = blockIdx.x * blockDim.x + threadIdx.x;
    int dir = (i >= TT*64) ? 1 : 0;
    int j = i - dir * (TT*64);
    float s = (g_xpart[dir][0][j] + g_xpart[dir][1][j])
            + (g_xpart[dir][2][j] + g_xpart[dir][3][j]);
    g_xdbl[dir][j] = s;
}

// ---------------- LN(cwln) + sigmoid + clip ----------------
__global__ void k_cwln(const float* __restrict__ g, const float* __restrict__ b) {
    __shared__ float sm[32];
    int t = blockIdx.x, c = threadIdx.x;
    float v = g_weight[t*CC + c];
    float2 s = blockReduce2<8>(v, v*v, sm);
    float m = s.x * (1.f/CC);
    float var = s.y * (1.f/CC) - m*m;
    float x = (v - m) * rsqrtf(var + 1e-5f) * g[c] + b[c];
    float w = 1.f / (1.f + __expf(-x));
    w = fminf(fmaxf(w, 0.01f), 0.99f);
    g_weight[t*CC + c] = w;
}

// ---------------- depthwise causal conv + silu (+ bf16 split of u) ----------------
#define CONV_CHUNK 64
__global__ void k_conv(const float* __restrict__ cwf, const float* __restrict__ cbf,
                       const float* __restrict__ cwb, const float* __restrict__ cbb) {
    int d = threadIdx.x;
    int b = blockIdx.y;
    int dir = blockIdx.z;
    int t0 = blockIdx.x * CONV_CHUNK;
    const float* w = dir ? cwb : cwf;
    float w0 = w[d*4+0], w1 = w[d*4+1], w2 = w[d*4+2], w3 = w[d*4+3];
    float bias = (dir ? cbb : cbf)[d];
    size_t base = (size_t)b * LL;

    auto fetch = [&](int t) -> float {
        if (t < 0) return 0.f;
        int l = dir ? (LL - 1 - t) : t;
        return g_xz[(base + l)*1024 + d];
    };

    float r0 = fetch(t0-3), r1 = fetch(t0-2), r2 = fetch(t0-1);
    float* uo = g_u[dir];
    __nv_bfloat16* uh = g_uh[dir];
    __nv_bfloat16* ul = g_ul[dir];
    #pragma unroll 4
    for (int i = 0; i < CONV_CHUNK; i++) {
        int t = t0 + i;
        float x3 = fetch(t);
        float accv = bias + w0*r0 + w1*r1 + w2*r2 + w3*x3;
        float s = siluf(accv);
        size_t idx = (base + t)*DI + d;
        uo[idx] = s;
        split1(s, uh[idx], ul[idx]);
        r0 = r1; r1 = r2; r2 = x3;
    }
}

// ---------------- selective scan ----------------
__global__ void k_scan(const float* __restrict__ Alf, const float* __restrict__ Alb,
                       const float* __restrict__ Df,  const float* __restrict__ Db) {
    int gid = blockIdx.x * blockDim.x + threadIdx.x;
    int l   = gid & 7;
    int d   = (gid >> 3) & 511;
    int b   = (gid >> 12) & 3;
    int dir = (gid >> 14) & 1;
    const unsigned full = 0xffffffffu;

    const float* Al = dir ? Alb : Alf;
    float a0 = -__expf(Al[d*DS + l*2 + 0]);
    float a1 = -__expf(Al[d*DS + l*2 + 1]);
    float Dv = (dir ? Db : Df)[d];

    const float* dl = g_delta[dir];
    const float* uu = g_u[dir];
    const float* xd = g_xdbl[dir];
    float* yo = g_y[dir];

    size_t base = (size_t)b * LL;
    float h0 = 0.f, h1 = 0.f;

    float  cd[4], cu[4], cz[4];
    float2 cB[4], cC[4];
    #pragma unroll
    for (int j = 0; j < 4; j++) {
        size_t row = base + j;
        cd[j] = dl[row*DI + d];
        cu[j] = uu[row*DI + d];
        cB[j] = *reinterpret_cast<const float2*>(xd + row*64 + 32 + l*2);
        cC[j] = *reinterpret_cast<const float2*>(xd + row*64 + 48 + l*2);
        int lq = dir ? (LL - 1 - j) : j;
        cz[j] = g_xz[(base + lq)*1024 + DI + d];
    }

    for (int t0 = 0; t0 < LL; t0 += 4) {
        float  nd[4] = {0,0,0,0}, nu[4] = {0,0,0,0}, nz[4] = {0,0,0,0};
        float2 nB[4] = {}, nC[4] = {};
        if (t0 + 4 < LL) {
            #pragma unroll
            for (int j = 0; j < 4; j++) {
                size_t row = base + t0 + 4 + j;
                nd[j] = dl[row*DI + d];
                nu[j] = uu[row*DI + d];
                nB[j] = *reinterpret_cast<const float2*>(xd + row*64 + 32 + l*2);
                nC[j] = *reinterpret_cast<const float2*>(xd + row*64 + 48 + l*2);
                int lq = dir ? (LL - 1 - (t0 + 4 + j)) : (t0 + 4 + j);
                nz[j] = g_xz[(base + lq)*1024 + DI + d];
            }
        }
        #pragma unroll
        for (int j = 0; j < 4; j++) {
            int t = t0 + j;
            float delta = cd[j], u = cu[j];
            float du = delta * u;
            h0 = fmaf(__expf(delta * a0), h0, du * cB[j].x);
            h1 = fmaf(__expf(delta * a1), h1, du * cB[j].y);
            float y = h0 * cC[j].x + h1 * cC[j].y;
            y += __shfl_xor_sync(full, y, 1);
            y += __shfl_xor_sync(full, y, 2);
            y += __shfl_xor_sync(full, y, 4);
            y = fmaf(Dv, u, y);
            y *= siluf(cz[j]);
            if (l == 0) yo[(base + t)*DI + d] = y;
        }
        #pragma unroll
        for (int j = 0; j < 4; j++) {
            cd[j] = nd[j]; cu[j] = nu[j]; cz[j] = nz[j];
            cB[j] = nB[j]; cC[j] = nC[j];
        }
    }
}

// ---------------- combine directions + mnorm LN -> bf16 split ----------------
__global__ void k_combine(const float* __restrict__ g, const float* __restrict__ b_) {
    __shared__ float sm[32];
    int t = blockIdx.x;
    int b = t >> 10, l = t & (LL - 1);
    int d = threadIdx.x;
    float v = 0.5f * (g_y[0][(size_t)t*DI + d] +
                      g_y[1][((size_t)b*LL + (LL - 1 - l))*DI + d]);
    float2 s = blockReduce2<16>(v, v*v, sm);
    float m = s.x * (1.f/DI);
    float var = s.y * (1.f/DI) - m*m;
    float x = (v - m) * rsqrtf(var + 1e-5f) * g[d] + b_[d];
    split1(x, g_abh[(size_t)t*DI + d], g_abl[(size_t)t*DI + d]);
}

// ---------------- pnorm LN -> bf16 split ----------------
__global__ void k_pnorm(const float* __restrict__ g, const float* __restrict__ b) {
    __shared__ float sm[32];
    int t = blockIdx.x, d = threadIdx.x;
    float v = g_o1[(size_t)t*DM + d];
    float2 s = blockReduce2<16>(v, v*v, sm);
    float m = s.x * (1.f/DM);
    float var = s.y * (1.f/DM) - m*m;
    float x = (v - m) * rsqrtf(var + 1e-5f) * g[d] + b[d];
    split1(x, g_abh[(size_t)t*DM + d], g_abl[(size_t)t*DM + d]);
}

// ---------------- final blend ----------------
__global__ void k_final(const float* __restrict__ i0, float* __restrict__ out) {
    int idx = blockIdx.x * blockDim.x + threadIdx.x;
    float v = cleanf(g_o2[idx]);
    float w = g_weight[idx];
    out[idx] = v*w + g_x0n[idx]*(1.f - w) + cleanf(i0[idx]);
}

// ---------------- launch ----------------
extern "C" void kernel_launch(void* const* d_in, const int* in_sizes, int n_in,
                              void* d_out, int out_size) {
    const float* input0   = (const float*)d_in[0];
    const float* input1   = (const float*)d_in[1];
    const float* norm0_g  = (const float*)d_in[2];
    const float* norm0_b  = (const float*)d_in[3];
    const float* norm1_g  = (const float*)d_in[4];
    const float* norm1_b  = (const float*)d_in[5];
    const float* in_proj_w= (const float*)d_in[6];

    const float *convf_w, *convf_b, *convb_w, *convb_b;
    const float *xprojf_w, *xprojb_w, *dtf_w, *dtf_b, *dtb_w, *dtb_b;
    const float *A_log_f, *A_log_b, *D_f, *D_b;
    const float *mnorm_g, *mnorm_b, *outproj_w, *pnorm_g, *pnorm_b;
    const float *projback_w, *projback_b, *cw_w, *cw_b, *cwln_g, *cwln_b;

    if (in_sizes[9] == 2048) {
        convf_w    = (const float*)d_in[7];
        convf_b    = (const float*)d_in[8];
        convb_w    = (const float*)d_in[9];
        convb_b    = (const float*)d_in[10];
        xprojf_w   = (const float*)d_in[11];
        xprojb_w   = (const float*)d_in[12];
        dtf_w      = (const float*)d_in[13];
        dtf_b      = (const float*)d_in[14];
        dtb_w      = (const float*)d_in[15];
        dtb_b      = (const float*)d_in[16];
        A_log_f    = (const float*)d_in[17];
        A_log_b    = (const float*)d_in[18];
        D_f        = (const float*)d_in[19];
        D_b        = (const float*)d_in[20];
    } else {
        // setup_inputs dict-insertion order (confirmed on HW)
        convf_w    = (const float*)d_in[7];
        convf_b    = (const float*)d_in[8];
        xprojf_w   = (const float*)d_in[9];
        dtf_w      = (const float*)d_in[10];
        dtf_b      = (const float*)d_in[11];
        A_log_f    = (const float*)d_in[12];
        D_f        = (const float*)d_in[13];
        convb_w    = (const float*)d_in[14];
        convb_b    = (const float*)d_in[15];
        xprojb_w   = (const float*)d_in[16];
        dtb_w      = (const float*)d_in[17];
        dtb_b      = (const float*)d_in[18];
        A_log_b    = (const float*)d_in[19];
        D_b        = (const float*)d_in[20];
    }
    mnorm_g    = (const float*)d_in[21];
    mnorm_b    = (const float*)d_in[22];
    outproj_w  = (const float*)d_in[23];
    pnorm_g    = (const float*)d_in[24];
    pnorm_b    = (const float*)d_in[25];
    projback_w = (const float*)d_in[26];
    projback_b = (const float*)d_in[27];
    cw_w       = (const float*)d_in[28];
    cw_b       = (const float*)d_in[29];
    cwln_g     = (const float*)d_in[30];
    cwln_b     = (const float*)d_in[31];
    float* out = (float*)d_out;

    float *weight, *xz, *u0, *xdbl0, *xpart, *delta0, *o1, *o2;
    __nv_bfloat16 *abh, *abl, *cwh, *cwl, *iph, *ipl, *oph, *opl, *pbh, *pbl;
    __nv_bfloat16 *uh, *ul, *xwh, *xwl;
    cudaGetSymbolAddress((void**)&weight,   g_weight);
    cudaGetSymbolAddress((void**)&xz,       g_xz);
    cudaGetSymbolAddress((void**)&u0,       g_u);
    cudaGetSymbolAddress((void**)&xdbl0,    g_xdbl);
    cudaGetSymbolAddress((void**)&xpart,    g_xpart);
    cudaGetSymbolAddress((void**)&delta0,   g_delta);
    cudaGetSymbolAddress((void**)&o1,       g_o1);
    cudaGetSymbolAddress((void**)&o2,       g_o2);
    cudaGetSymbolAddress((void**)&abh,      g_abh);
    cudaGetSymbolAddress((void**)&abl,      g_abl);
    cudaGetSymbolAddress((void**)&cwh,      g_cwh);
    cudaGetSymbolAddress((void**)&cwl,      g_cwl);
    cudaGetSymbolAddress((void**)&iph,      g_iph);
    cudaGetSymbolAddress((void**)&ipl,      g_ipl);
    cudaGetSymbolAddress((void**)&oph,      g_oph);
    cudaGetSymbolAddress((void**)&opl,      g_opl);
    cudaGetSymbolAddress((void**)&pbh,      g_pbh);
    cudaGetSymbolAddress((void**)&pbl,      g_pbl);
    cudaGetSymbolAddress((void**)&uh,       g_uh);
    cudaGetSymbolAddress((void**)&ul,       g_ul);
    cudaGetSymbolAddress((void**)&xwh,      g_xwh);
    cudaGetSymbolAddress((void**)&xwl,      g_xwl);
    float* xdbl1  = xdbl0  + (size_t)TT*64;
    float* xpart0 = xpart;
    float* xpart1 = xpart  + (size_t)4*TT*64;
    float* delta1 = delta0 + (size_t)TT*DI;
    __nv_bfloat16* uh0 = uh;
    __nv_bfloat16* uh1 = uh + (size_t)TT*DI;
    __nv_bfloat16* ul0 = ul;
    __nv_bfloat16* ul1 = ul + (size_t)TT*DI;
    __nv_bfloat16* xwh0 = xwh;
    __nv_bfloat16* xwh1 = xwh + (size_t)64*DI;
    __nv_bfloat16* xwl0 = xwl;
    __nv_bfloat16* xwl1 = xwl + (size_t)64*DI;

    // 0. split all weights (one kernel)
    k_split_w<<<1088, 256>>>(cw_w, in_proj_w, outproj_w, projback_w, xprojf_w, xprojb_w);

    // 1. input LayerNorms -> x0n + bf16 split of combined
    k_ln_inputs<<<TT, 256>>>(input0, input1, norm0_g, norm0_b, norm1_g, norm1_b);

    // 2. cw GEMM (tensor): (4096x512)@(256x512)^T + bias
    k_gemm_bf16<64,1,0><<<dim3(CC/64, TT/64), 128>>>(abh, abl, cwh, cwl, cw_b, weight, CC, DM, DM);
    // 3. cw LN + sigmoid + clip
    k_cwln<<<TT, 256>>>(cwln_g, cwln_b);

    // 4. in_proj GEMM (tensor): (4096x512)@(1024x512)^T
    k_gemm_bf16<128,0,0><<<dim3(1024/64, TT/128), 256>>>(abh, abl, iph, ipl, nullptr, xz, 1024, DM, DM);

    // 5. conv + silu + bf16 split of u, both directions
    k_conv<<<dim3(LL/CONV_CHUNK, BB, 2), 512>>>(convf_w, convf_b, convb_w, convb_b);

    // 6. x_dbl GEMMs (tensor, split-K 4), then reduce
    k_gemm_bf16<64,0,1><<<dim3(1, TT/64, 4), 128>>>(uh0, ul0, xwh0, xwl0, nullptr, xpart0, 64, DI, 128);
    k_gemm_bf16<64,0,1><<<dim3(1, TT/64, 4), 128>>>(uh1, ul1, xwh1, xwl1, nullptr, xpart1, 64, DI, 128);
    k_xreduce<<<2*TT*64/256, 256>>>();

    // 7. delta GEMMs (SIMT, K=32): (4096x32)@(512x32)^T + bias, softplus
    k_gemm<128,64,16,8,8,2><<<dim3(DI/64, TT/128), 128>>>(xdbl0, 64, dtf_w, DR, dtf_b, delta0, DI, DR);
    k_gemm<128,64,16,8,8,2><<<dim3(DI/64, TT/128), 128>>>(xdbl1, 64, dtb_w, DR, dtb_b, delta1, DI, DR);

    // 8. selective scan
    k_scan<<<128, 256>>>(A_log_f, A_log_b, D_f, D_b);

    // 9. combine + mnorm -> bf16 split
    k_combine<<<TT, 512>>>(mnorm_g, mnorm_b);

    // 10. out_proj GEMM (tensor): (4096x512)@(512x512)^T
    k_gemm_bf16<128,0,0><<<dim3(DM/64, TT/128), 256>>>(abh, abl, oph, opl, nullptr, o1, DM, DI, DI);

    // 11. pnorm -> bf16 split
    k_pnorm<<<TT, 512>>>(pnorm_g, pnorm_b);

    // 12. projback GEMM (tensor): (4096x512)@(256x512)^T + bias
    k_gemm_bf16<64,1,0><<<dim3(CC/64, TT/64), 128>>>(abh, abl, pbh, pbl, projback_b, o2, CC, DM, DM);

    // 13. final blend
    k_final<<<TT, 256>>>(input0, out);
}